// round 10
// baseline (speedup 1.0000x reference)
#include <cuda_runtime.h>

typedef unsigned long long ull;

__device__ __forceinline__ ull pack2(float lo, float hi) {
    ull r; asm("mov.b64 %0, {%1, %2};" : "=l"(r) : "f"(lo), "f"(hi)); return r;
}
__device__ __forceinline__ void unpack2(ull v, float& lo, float& hi) {
    asm("mov.b64 {%0, %1}, %2;" : "=f"(lo), "=f"(hi) : "l"(v));
}
__device__ __forceinline__ void fma2(ull& d, ull a, ull b) {
    asm("fma.rn.f32x2 %0, %1, %2, %0;" : "+l"(d) : "l"(a), "l"(b));
}
__device__ __forceinline__ float ex2f(float x) {
    float y; asm("ex2.approx.f32 %0, %1;" : "=f"(y) : "f"(x)); return y;
}

// ---------------- scratch (no allocations allowed) ----------------
#define NTOK (2*4096)              // 8192 tokens
#define PBUF (NTOK*64)             // 524288 floats per partial buffer
__device__ float g_xt[PBUF];       // x in NHWC
__device__ float g_p[8*PBUF];      // conv1 partials (per ci-eighth)
__device__ float g_q[8*PBUF];      // conv2 partials (per ci-eighth)
__device__ float g_wt1[64*9*64];   // [ci][k][(co2,s)]: pair = (co2, co2+32)
__device__ float g_wt2[64*9*64];

// ---------------- prep: NCHW -> NHWC transpose of x ----------------
__global__ void k_transpose_x(const float* __restrict__ x) {
    __shared__ float tile[32][33];
    int b  = blockIdx.z;
    int c0 = blockIdx.y * 32;
    int s0 = blockIdx.x * 32;
    int tx = threadIdx.x, ty = threadIdx.y;
#pragma unroll
    for (int i = 0; i < 32; i += 8)
        tile[ty + i][tx] = x[(b*64 + c0 + ty + i) * 4096 + s0 + tx];
    __syncthreads();
#pragma unroll
    for (int i = 0; i < 32; i += 8)
        g_xt[(b*4096 + s0 + ty + i) * 64 + c0 + tx] = tile[tx][ty + i];
}

// ---- prep: [co][ci][3][3] -> [ci][k][(co2,s)] where pair = (co2, co2+32) ----
__global__ void k_transpose_w(const float* __restrict__ w1, const float* __restrict__ w2) {
    int i = blockIdx.x * blockDim.x + threadIdx.x;
    if (i >= 2 * 36864) return;
    const float* w = (i < 36864) ? w1 : w2;
    float* dst     = (i < 36864) ? g_wt1 : g_wt2;
    int o   = (i < 36864) ? i : (i - 36864);
    int ci  = o / 576;
    int rem = o - ci * 576;
    int kk  = rem >> 6;
    int qq  = rem & 63;
    int co2 = qq >> 1;
    int s   = qq & 1;
    dst[o] = w[(s * 32 + co2) * 576 + ci * 9 + kk];
}

// ---------------- partial conv3x3: 8 ci x 64 co per block ----------------
// 128 threads = 32 co-pairs x 4 px-groups; thread: 2 rows x 8 px x (co2,co2+32).
// tile 2 rows x 32 px. grid (2,32,16): z = b*8 + eighth. smem staged once, 1 barrier.
// SRC=0: in = g_xt; out = g_p[eighth].  SRC=1: in = relu(Σ8 g_p + b1); out = g_q[eighth]
#define IN_CI_STRIDE 148   // 4 rows * 36 + pad, 16B-aligned
template<int SRC>
__global__ void __launch_bounds__(128, 6) k_conv(const float* __restrict__ in_bias) {
    const float* __restrict__ wt = (SRC == 0) ? g_wt1 : g_wt2;

    __shared__ float w_s[8 * 576];               // 8 ci x 9 k x 64 (pair-interleaved)
    __shared__ float in_s[8 * IN_CI_STRIDE];     // [ci8][r*36 + xx], r<4, xx<34

    const int tid = threadIdx.x;
    const int co2 = tid & 31;
    const int h   = tid >> 5;                    // 8-px group 0..3, uniform per warp
    const int x0 = blockIdx.x * 32, y0 = blockIdx.y * 2;
    const int b      = blockIdx.z >> 3;
    const int eighth = blockIdx.z & 7;

    // ---- stage weights: 8 ci x 576 = 4608 floats = 1152 float4
    {
        const float4* wsrc = (const float4*)(wt + eighth * 8 * 576);
        float4* wdst = (float4*)w_s;
#pragma unroll
        for (int i = 0; i < 9; i++)
            wdst[tid + i * 128] = wsrc[tid + i * 128];
    }
    // ---- stage inputs: 4 rows x 34 px x 8 ci = 1088 elems
    {
        const int ci8 = tid & 7;                 // fast index -> coalesced LDG
        float bvin = 0.f;
        if (SRC == 1) bvin = in_bias[eighth * 8 + ci8];
#pragma unroll
        for (int i = 0; i < 9; i++) {
            int e = i * 128 + tid;
            if (e < 1088) {
                int t  = e >> 3;                 // 0..135
                int r  = t / 34;
                int xx = t - r * 34;
                int y  = y0 - 1 + r;
                int xg = x0 - 1 + xx;
                float v = 0.f;
                if ((unsigned)y < 64u && (unsigned)xg < 64u) {
                    int idx = ((b * 64 + y) * 64 + xg) * 64 + eighth * 8 + ci8;
                    if (SRC == 0) {
                        v = g_xt[idx];
                    } else {
                        float s0 = g_p[idx]          + g_p[idx + PBUF];
                        float s1 = g_p[idx + 2*PBUF] + g_p[idx + 3*PBUF];
                        float s2 = g_p[idx + 4*PBUF] + g_p[idx + 5*PBUF];
                        float s3 = g_p[idx + 6*PBUF] + g_p[idx + 7*PBUF];
                        v = fmaxf((s0 + s1) + (s2 + s3) + bvin, 0.f);
                    }
                }
                in_s[ci8 * IN_CI_STRIDE + r * 36 + xx] = v;
            }
        }
    }
    __syncthreads();

    ull accA[8] = {0,0,0,0,0,0,0,0};             // row y0
    ull accB[8] = {0,0,0,0,0,0,0,0};             // row y0+1

#pragma unroll
    for (int ci = 0; ci < 8; ci++) {
        const ull* wp = (const ull*)(w_s + ci * 576) + co2;
        ull w2[9];
#pragma unroll
        for (int k = 0; k < 9; k++) w2[k] = wp[k * 32];

        const float* ibase = in_s + ci * IN_CI_STRIDE + h * 8;
#pragma unroll
        for (int irow = 0; irow < 4; irow++) {
            float4 v0 = *(const float4*)(ibase + irow * 36);        // broadcast
            float4 v1 = *(const float4*)(ibase + irow * 36 + 4);    // broadcast
            float2 v2 = *(const float2*)(ibase + irow * 36 + 8);    // broadcast
            ull d[10];
            d[0] = pack2(v0.x, v0.x); d[1] = pack2(v0.y, v0.y);
            d[2] = pack2(v0.z, v0.z); d[3] = pack2(v0.w, v0.w);
            d[4] = pack2(v1.x, v1.x); d[5] = pack2(v1.y, v1.y);
            d[6] = pack2(v1.z, v1.z); d[7] = pack2(v1.w, v1.w);
            d[8] = pack2(v2.x, v2.x); d[9] = pack2(v2.y, v2.y);
            if (irow < 3) {          // row A, dy = irow
#pragma unroll
                for (int p = 0; p < 8; p++) {
                    fma2(accA[p], w2[irow*3+0], d[p]);
                    fma2(accA[p], w2[irow*3+1], d[p+1]);
                    fma2(accA[p], w2[irow*3+2], d[p+2]);
                }
            }
            if (irow >= 1) {         // row B, dy = irow-1
#pragma unroll
                for (int p = 0; p < 8; p++) {
                    fma2(accB[p], w2[(irow-1)*3+0], d[p]);
                    fma2(accB[p], w2[(irow-1)*3+1], d[p+1]);
                    fma2(accB[p], w2[(irow-1)*3+2], d[p+2]);
                }
            }
        }
    }

    float* __restrict__ out = ((SRC == 0) ? g_p : g_q) + eighth * PBUF;
    int base = ((b * 64 + y0) * 64 + x0 + h * 8) * 64;
#pragma unroll
    for (int p = 0; p < 8; p++) {
        float a0, a1, b0v, b1v;
        unpack2(accA[p], a0, a1);
        unpack2(accB[p], b0v, b1v);
        out[base + p * 64 + co2]             = a0;   // row y0
        out[base + p * 64 + co2 + 32]        = a1;
        out[base + 4096 + p * 64 + co2]      = b0v;  // row y0+1
        out[base + 4096 + p * 64 + co2 + 32] = b1v;
    }
}

// ---------------- attention: 32 tokens/block, 256 threads (unchanged) ----------------
#define W_STRIDE 66
#define T_STRIDE 65
#define OFF_WQ 0
#define OFF_WK (64*W_STRIDE)
#define OFF_WV (2*64*W_STRIDE)
#define OFF_WO (3*64*W_STRIDE)
#define OFF_T  (4*64*W_STRIDE)
#define OFF_K  (OFF_T + 32*T_STRIDE)
#define OFF_V  (OFF_K + 32*T_STRIDE)
#define OFF_O  (OFF_V + 32*T_STRIDE)
#define OFF_SQ (OFF_O + 32*T_STRIDE)
#define OFF_SK (OFF_SQ + 8*33)
#define SMEM_FLOATS (OFF_SK + 8*33)

__global__ void __launch_bounds__(256) k_attn(
    const float* __restrict__ wq, const float* __restrict__ wk,
    const float* __restrict__ wv, const float* __restrict__ wo,
    const float* __restrict__ bo, const float* __restrict__ b2,
    float* __restrict__ out)
{
    extern __shared__ float sm[];
    float* wq_s = sm + OFF_WQ;
    float* wk_s = sm + OFF_WK;
    float* wv_s = sm + OFF_WV;
    float* wo_s = sm + OFF_WO;
    float* t_s  = sm + OFF_T;
    float* k_s  = sm + OFF_K;
    float* v_s  = sm + OFF_V;
    float* o_s  = sm + OFF_O;
    float* sq_s = sm + OFF_SQ;
    float* sk_s = sm + OFF_SK;

    int tid = threadIdx.x;
    int n0  = blockIdx.x * 32;

#pragma unroll 4
    for (int i = 0; i < 16; i++) {
        int gg = tid + i * 256;
        int c = gg >> 6, l = gg & 63;
        wq_s[l * W_STRIDE + c] = wq[gg];
        wk_s[l * W_STRIDE + c] = wk[gg];
        wv_s[l * W_STRIDE + c] = wv[gg];
        wo_s[l * W_STRIDE + c] = wo[gg];
    }
    // t = sum of 8 conv2 partials + bias2
#pragma unroll
    for (int i = 0; i < 8; i++) {
        int gg = tid + i * 256;
        int idx = n0 * 64 + gg;
        float s0 = g_q[idx]          + g_q[idx + PBUF];
        float s1 = g_q[idx + 2*PBUF] + g_q[idx + 3*PBUF];
        float s2 = g_q[idx + 4*PBUF] + g_q[idx + 5*PBUF];
        float s3 = g_q[idx + 6*PBUF] + g_q[idx + 7*PBUF];
        float tv = (s0 + s1) + (s2 + s3) + b2[gg & 63];
        t_s[(gg >> 6) * T_STRIDE + (gg & 63)] = tv;
    }
    __syncthreads();

    const int tt = tid & 31;
    const int cg = tid >> 5;
    const int c0 = cg * 8;

    ull q2[4], k2[4], v2[4];
#pragma unroll
    for (int j = 0; j < 4; j++) { q2[j] = 0ull; k2[j] = 0ull; v2[j] = 0ull; }
    const float* trow = t_s + tt * T_STRIDE;
#pragma unroll 4
    for (int l = 0; l < 64; l++) {
        float tl = trow[l];
        ull tl2 = pack2(tl, tl);
        const ull* wql = (const ull*)(wq_s + l * W_STRIDE + c0);
        const ull* wkl = (const ull*)(wk_s + l * W_STRIDE + c0);
        const ull* wvl = (const ull*)(wv_s + l * W_STRIDE + c0);
#pragma unroll
        for (int j = 0; j < 4; j++) {
            fma2(q2[j], tl2, wql[j]);
            fma2(k2[j], tl2, wkl[j]);
            fma2(v2[j], tl2, wvl[j]);
        }
    }
    float q[8], kk[8], vv[8];
#pragma unroll
    for (int j = 0; j < 4; j++) {
        unpack2(q2[j], q[2*j], q[2*j+1]);
        unpack2(k2[j], kk[2*j], kk[2*j+1]);
        unpack2(v2[j], vv[2*j], vv[2*j+1]);
    }
    float sq = 0.f, sk = 0.f;
#pragma unroll
    for (int j = 0; j < 8; j++) { sq = fmaf(q[j], q[j], sq); sk = fmaf(kk[j], kk[j], sk); }
    sq_s[cg * 33 + tt] = sq;
    sk_s[cg * 33 + tt] = sk;
    __syncthreads();
    sq = 0.f; sk = 0.f;
#pragma unroll
    for (int m = 0; m < 8; m++) { sq += sq_s[m * 33 + tt]; sk += sk_s[m * 33 + tt]; }
    const float LOG2E = 1.4426950408889634f;
    float invq = LOG2E / fmaxf(sqrtf(sq), 1e-12f);
    float invk = 1.0f  / fmaxf(sqrtf(sk), 1e-12f);
#pragma unroll
    for (int j = 0; j < 8; j++) {
        q[j] *= invq;
        k_s[tt * T_STRIDE + c0 + j] = kk[j] * invk;
        v_s[tt * T_STRIDE + c0 + j] = vv[j];
    }
    __syncthreads();

    float num[8], den[8];
#pragma unroll
    for (int j = 0; j < 8; j++) { num[j] = 0.f; den[j] = 0.f; }
    const float* krow = k_s + tt * T_STRIDE;
    const float* vrow = v_s + tt * T_STRIDE;
#pragma unroll 2
    for (int d = 0; d < 64; d++) {
        float kd = krow[d];
        float vd = vrow[d];
#pragma unroll
        for (int j = 0; j < 8; j++) {
            float e = ex2f(q[j] * kd);
            num[j] = fmaf(e, vd, num[j]);
            den[j] += e;
        }
    }
#pragma unroll
    for (int j = 0; j < 8; j++)
        o_s[tt * T_STRIDE + c0 + j] = __fdividef(num[j], den[j]);
    __syncthreads();

    ull fin2[4];
#pragma unroll
    for (int j = 0; j < 4; j++) fin2[j] = 0ull;
    const float* orow = o_s + tt * T_STRIDE;
#pragma unroll 4
    for (int c = 0; c < 64; c++) {
        float oc = orow[c];
        ull oc2 = pack2(oc, oc);
        const ull* wol = (const ull*)(wo_s + c * W_STRIDE + c0);
#pragma unroll
        for (int j = 0; j < 4; j++) fma2(fin2[j], oc2, wol[j]);
    }
    int b = n0 >> 12;
    int s = (n0 & 4095) + tt;
#pragma unroll
    for (int j = 0; j < 4; j++) {
        float f0, f1;
        unpack2(fin2[j], f0, f1);
        int ch = c0 + 2 * j;
        f0 += bo[ch]     + t_s[tt * T_STRIDE + ch];
        f1 += bo[ch + 1] + t_s[tt * T_STRIDE + ch + 1];
        out[(b * 64 + ch    ) * 4096 + s] = f0;
        out[(b * 64 + ch + 1) * 4096 + s] = f1;
    }
}

// ---------------- launch ----------------
extern "C" void kernel_launch(void* const* d_in, const int* in_sizes, int n_in,
                              void* d_out, int out_size) {
    const float* x  = (const float*)d_in[0];
    const float* w1 = (const float*)d_in[1];
    const float* b1 = (const float*)d_in[2];
    const float* w2 = (const float*)d_in[3];
    const float* b2 = (const float*)d_in[4];
    const float* wq = (const float*)d_in[5];
    const float* wk = (const float*)d_in[6];
    const float* wv = (const float*)d_in[7];
    const float* wo = (const float*)d_in[8];
    const float* bo = (const float*)d_in[9];
    float* out = (float*)d_out;

    cudaFuncSetAttribute(k_attn, cudaFuncAttributeMaxDynamicSharedMemorySize,
                         SMEM_FLOATS * (int)sizeof(float));

    k_transpose_x<<<dim3(128, 2, 2), dim3(32, 8)>>>(x);
    k_transpose_w<<<(2 * 36864 + 255) / 256, 256>>>(w1, w2);
    k_conv<0><<<dim3(2, 32, 16), dim3(128)>>>(nullptr);  // conv1 partials (8 ci each)
    k_conv<1><<<dim3(2, 32, 16), dim3(128)>>>(b1);       // conv2 partials, fused relu(Σ+b1)
    k_attn<<<256, 256, SMEM_FLOATS * (int)sizeof(float)>>>(wq, wk, wv, wo, bo, b2, out);
}

// round 11
// speedup vs baseline: 1.0632x; 1.0632x over previous
#include <cuda_runtime.h>

typedef unsigned long long ull;

__device__ __forceinline__ ull pack2(float lo, float hi) {
    ull r; asm("mov.b64 %0, {%1, %2};" : "=l"(r) : "f"(lo), "f"(hi)); return r;
}
__device__ __forceinline__ void unpack2(ull v, float& lo, float& hi) {
    asm("mov.b64 {%0, %1}, %2;" : "=f"(lo), "=f"(hi) : "l"(v));
}
__device__ __forceinline__ void fma2(ull& d, ull a, ull b) {
    asm("fma.rn.f32x2 %0, %1, %2, %0;" : "+l"(d) : "l"(a), "l"(b));
}
__device__ __forceinline__ float ex2f(float x) {
    float y; asm("ex2.approx.f32 %0, %1;" : "=f"(y) : "f"(x)); return y;
}

// ---------------- scratch (no allocations allowed) ----------------
#define NTOK (2*4096)              // 8192 tokens
#define PBUF (NTOK*64)             // 524288 floats per partial buffer
__device__ float g_p[4*PBUF];      // conv1 partials (per ci-quarter)
__device__ float g_q[4*PBUF];      // conv2 partials (per ci-quarter)
__device__ float g_wt1[64*9*64];   // [ci][k][(co2,s)]: pair = (co2, co2+32)
__device__ float g_wt2[64*9*64];

// ---- prep: [co][ci][3][3] -> [ci][k][(co2,s)] where pair = (co2, co2+32) ----
__global__ void k_transpose_w(const float* __restrict__ w1, const float* __restrict__ w2) {
    int i = blockIdx.x * blockDim.x + threadIdx.x;
    if (i >= 2 * 36864) return;
    const float* w = (i < 36864) ? w1 : w2;
    float* dst     = (i < 36864) ? g_wt1 : g_wt2;
    int o   = (i < 36864) ? i : (i - 36864);
    int ci  = o / 576;
    int rem = o - ci * 576;
    int kk  = rem >> 6;
    int qq  = rem & 63;
    int co2 = qq >> 1;
    int s   = qq & 1;
    dst[o] = w[(s * 32 + co2) * 576 + ci * 9 + kk];
}

// ---------------- partial conv3x3: 16 ci x 64 co per block ----------------
// 256 threads = 32 co-pairs x 8 px-groups; thread: 2 rows x 4 px x (co2,co2+32).
// tile 2 rows x 32 px. grid (2,32,8): z = b*4 + quarter. smem staged once, 1 barrier.
// SRC=0: in = x (NCHW, direct); out = g_p[quarter].
// SRC=1: in = relu(Σ4 g_p + b1) (NHWC); out = g_q[quarter].
#define IN_CI_STRIDE 148   // 4 rows * 36 + pad, 16B-aligned
template<int SRC>
__global__ void __launch_bounds__(256, 3) k_conv(const float* __restrict__ in_x,
                                                 const float* __restrict__ in_bias) {
    const float* __restrict__ wt = (SRC == 0) ? g_wt1 : g_wt2;

    __shared__ float w_s[16 * 576];              // 16 ci x 9 k x 64 (pair-interleaved)
    __shared__ float in_s[16 * IN_CI_STRIDE];    // [ci16][r*36 + xx], r<4, xx<34

    const int tid = threadIdx.x;
    const int co2 = tid & 31;
    const int h   = tid >> 5;                    // 4-px group 0..7
    const int x0 = blockIdx.x * 32, y0 = blockIdx.y * 2;
    const int b       = blockIdx.z >> 2;
    const int quarter = blockIdx.z & 3;

    // ---- stage weights: 16 ci x 576 = 9216 floats = 2304 float4
    {
        const float4* wsrc = (const float4*)(wt + quarter * 16 * 576);
        float4* wdst = (float4*)w_s;
#pragma unroll
        for (int i = 0; i < 9; i++)
            wdst[tid + i * 256] = wsrc[tid + i * 256];
    }
    // ---- stage inputs: 16 ci x 4 rows x 34 px = 2176 elems
    if (SRC == 0) {
        // NCHW source: xx fastest across lanes -> coalesced
#pragma unroll
        for (int i = 0; i < 9; i++) {
            int e = i * 256 + tid;
            if (e < 2176) {
                int xx = e % 34;
                int t  = e / 34;                 // 0..63
                int r  = t & 3;
                int ci = t >> 2;
                int y  = y0 - 1 + r;
                int xg = x0 - 1 + xx;
                float v = 0.f;
                if ((unsigned)y < 64u && (unsigned)xg < 64u)
                    v = in_x[((b * 64 + quarter * 16 + ci) * 64 + y) * 64 + xg];
                in_s[ci * IN_CI_STRIDE + r * 36 + xx] = v;
            }
        }
    } else {
        // NHWC partials: ci fastest across lanes -> coalesced
        const int ci = tid & 15;
        const float bvin = in_bias[quarter * 16 + ci];
#pragma unroll
        for (int i = 0; i < 9; i++) {
            int e = i * 256 + tid;
            if (e < 2176) {
                int t  = e >> 4;                 // 0..135
                int r  = t / 34;
                int xx = t - r * 34;
                int y  = y0 - 1 + r;
                int xg = x0 - 1 + xx;
                float v = 0.f;
                if ((unsigned)y < 64u && (unsigned)xg < 64u) {
                    int idx = ((b * 64 + y) * 64 + xg) * 64 + quarter * 16 + ci;
                    float s0 = g_p[idx]          + g_p[idx + PBUF];
                    float s1 = g_p[idx + 2*PBUF] + g_p[idx + 3*PBUF];
                    v = fmaxf(s0 + s1 + bvin, 0.f);
                }
                in_s[ci * IN_CI_STRIDE + r * 36 + xx] = v;
            }
        }
    }
    __syncthreads();

    ull accA[4] = {0,0,0,0};                     // row y0
    ull accB[4] = {0,0,0,0};                     // row y0+1

#pragma unroll 4
    for (int ci = 0; ci < 16; ci++) {
        const ull* wp = (const ull*)(w_s + ci * 576) + co2;
        ull w2[9];
#pragma unroll
        for (int k = 0; k < 9; k++) w2[k] = wp[k * 32];

        const float* ibase = in_s + ci * IN_CI_STRIDE + h * 4;
#pragma unroll
        for (int irow = 0; irow < 4; irow++) {
            float4 v0 = *(const float4*)(ibase + irow * 36);        // broadcast
            float2 v1 = *(const float2*)(ibase + irow * 36 + 4);    // broadcast
            ull d[6];
            d[0] = pack2(v0.x, v0.x); d[1] = pack2(v0.y, v0.y);
            d[2] = pack2(v0.z, v0.z); d[3] = pack2(v0.w, v0.w);
            d[4] = pack2(v1.x, v1.x); d[5] = pack2(v1.y, v1.y);
            if (irow < 3) {          // row A, dy = irow
#pragma unroll
                for (int p = 0; p < 4; p++) {
                    fma2(accA[p], w2[irow*3+0], d[p]);
                    fma2(accA[p], w2[irow*3+1], d[p+1]);
                    fma2(accA[p], w2[irow*3+2], d[p+2]);
                }
            }
            if (irow >= 1) {         // row B, dy = irow-1
#pragma unroll
                for (int p = 0; p < 4; p++) {
                    fma2(accB[p], w2[(irow-1)*3+0], d[p]);
                    fma2(accB[p], w2[(irow-1)*3+1], d[p+1]);
                    fma2(accB[p], w2[(irow-1)*3+2], d[p+2]);
                }
            }
        }
    }

    float* __restrict__ out = ((SRC == 0) ? g_p : g_q) + quarter * PBUF;
    int base = ((b * 64 + y0) * 64 + x0 + h * 4) * 64;
#pragma unroll
    for (int p = 0; p < 4; p++) {
        float a0, a1, b0v, b1v;
        unpack2(accA[p], a0, a1);
        unpack2(accB[p], b0v, b1v);
        out[base + p * 64 + co2]             = a0;   // row y0
        out[base + p * 64 + co2 + 32]        = a1;
        out[base + 4096 + p * 64 + co2]      = b0v;  // row y0+1
        out[base + 4096 + p * 64 + co2 + 32] = b1v;
    }
}

// ---------------- attention: 32 tokens/block, 256 threads (unchanged) ----------------
#define W_STRIDE 66
#define T_STRIDE 65
#define OFF_WQ 0
#define OFF_WK (64*W_STRIDE)
#define OFF_WV (2*64*W_STRIDE)
#define OFF_WO (3*64*W_STRIDE)
#define OFF_T  (4*64*W_STRIDE)
#define OFF_K  (OFF_T + 32*T_STRIDE)
#define OFF_V  (OFF_K + 32*T_STRIDE)
#define OFF_O  (OFF_V + 32*T_STRIDE)
#define OFF_SQ (OFF_O + 32*T_STRIDE)
#define OFF_SK (OFF_SQ + 8*33)
#define SMEM_FLOATS (OFF_SK + 8*33)

__global__ void __launch_bounds__(256) k_attn(
    const float* __restrict__ wq, const float* __restrict__ wk,
    const float* __restrict__ wv, const float* __restrict__ wo,
    const float* __restrict__ bo, const float* __restrict__ b2,
    float* __restrict__ out)
{
    extern __shared__ float sm[];
    float* wq_s = sm + OFF_WQ;
    float* wk_s = sm + OFF_WK;
    float* wv_s = sm + OFF_WV;
    float* wo_s = sm + OFF_WO;
    float* t_s  = sm + OFF_T;
    float* k_s  = sm + OFF_K;
    float* v_s  = sm + OFF_V;
    float* o_s  = sm + OFF_O;
    float* sq_s = sm + OFF_SQ;
    float* sk_s = sm + OFF_SK;

    int tid = threadIdx.x;
    int n0  = blockIdx.x * 32;

#pragma unroll 4
    for (int i = 0; i < 16; i++) {
        int gg = tid + i * 256;
        int c = gg >> 6, l = gg & 63;
        wq_s[l * W_STRIDE + c] = wq[gg];
        wk_s[l * W_STRIDE + c] = wk[gg];
        wv_s[l * W_STRIDE + c] = wv[gg];
        wo_s[l * W_STRIDE + c] = wo[gg];
    }
    // t = sum of 4 conv2 partials + bias2
#pragma unroll
    for (int i = 0; i < 8; i++) {
        int gg = tid + i * 256;
        int idx = n0 * 64 + gg;
        float s0 = g_q[idx]          + g_q[idx + PBUF];
        float s1 = g_q[idx + 2*PBUF] + g_q[idx + 3*PBUF];
        t_s[(gg >> 6) * T_STRIDE + (gg & 63)] = s0 + s1 + b2[gg & 63];
    }
    __syncthreads();

    const int tt = tid & 31;
    const int cg = tid >> 5;
    const int c0 = cg * 8;

    ull q2[4], k2[4], v2[4];
#pragma unroll
    for (int j = 0; j < 4; j++) { q2[j] = 0ull; k2[j] = 0ull; v2[j] = 0ull; }
    const float* trow = t_s + tt * T_STRIDE;
#pragma unroll 4
    for (int l = 0; l < 64; l++) {
        float tl = trow[l];
        ull tl2 = pack2(tl, tl);
        const ull* wql = (const ull*)(wq_s + l * W_STRIDE + c0);
        const ull* wkl = (const ull*)(wk_s + l * W_STRIDE + c0);
        const ull* wvl = (const ull*)(wv_s + l * W_STRIDE + c0);
#pragma unroll
        for (int j = 0; j < 4; j++) {
            fma2(q2[j], tl2, wql[j]);
            fma2(k2[j], tl2, wkl[j]);
            fma2(v2[j], tl2, wvl[j]);
        }
    }
    float q[8], kk[8], vv[8];
#pragma unroll
    for (int j = 0; j < 4; j++) {
        unpack2(q2[j], q[2*j], q[2*j+1]);
        unpack2(k2[j], kk[2*j], kk[2*j+1]);
        unpack2(v2[j], vv[2*j], vv[2*j+1]);
    }
    float sq = 0.f, sk = 0.f;
#pragma unroll
    for (int j = 0; j < 8; j++) { sq = fmaf(q[j], q[j], sq); sk = fmaf(kk[j], kk[j], sk); }
    sq_s[cg * 33 + tt] = sq;
    sk_s[cg * 33 + tt] = sk;
    __syncthreads();
    sq = 0.f; sk = 0.f;
#pragma unroll
    for (int m = 0; m < 8; m++) { sq += sq_s[m * 33 + tt]; sk += sk_s[m * 33 + tt]; }
    const float LOG2E = 1.4426950408889634f;
    float invq = LOG2E / fmaxf(sqrtf(sq), 1e-12f);
    float invk = 1.0f  / fmaxf(sqrtf(sk), 1e-12f);
#pragma unroll
    for (int j = 0; j < 8; j++) {
        q[j] *= invq;
        k_s[tt * T_STRIDE + c0 + j] = kk[j] * invk;
        v_s[tt * T_STRIDE + c0 + j] = vv[j];
    }
    __syncthreads();

    float num[8], den[8];
#pragma unroll
    for (int j = 0; j < 8; j++) { num[j] = 0.f; den[j] = 0.f; }
    const float* krow = k_s + tt * T_STRIDE;
    const float* vrow = v_s + tt * T_STRIDE;
#pragma unroll 2
    for (int d = 0; d < 64; d++) {
        float kd = krow[d];
        float vd = vrow[d];
#pragma unroll
        for (int j = 0; j < 8; j++) {
            float e = ex2f(q[j] * kd);
            num[j] = fmaf(e, vd, num[j]);
            den[j] += e;
        }
    }
#pragma unroll
    for (int j = 0; j < 8; j++)
        o_s[tt * T_STRIDE + c0 + j] = __fdividef(num[j], den[j]);
    __syncthreads();

    ull fin2[4];
#pragma unroll
    for (int j = 0; j < 4; j++) fin2[j] = 0ull;
    const float* orow = o_s + tt * T_STRIDE;
#pragma unroll 4
    for (int c = 0; c < 64; c++) {
        float oc = orow[c];
        ull oc2 = pack2(oc, oc);
        const ull* wol = (const ull*)(wo_s + c * W_STRIDE + c0);
#pragma unroll
        for (int j = 0; j < 4; j++) fma2(fin2[j], oc2, wol[j]);
    }
    int b = n0 >> 12;
    int s = (n0 & 4095) + tt;
#pragma unroll
    for (int j = 0; j < 4; j++) {
        float f0, f1;
        unpack2(fin2[j], f0, f1);
        int ch = c0 + 2 * j;
        f0 += bo[ch]     + t_s[tt * T_STRIDE + ch];
        f1 += bo[ch + 1] + t_s[tt * T_STRIDE + ch + 1];
        out[(b * 64 + ch    ) * 4096 + s] = f0;
        out[(b * 64 + ch + 1) * 4096 + s] = f1;
    }
}

// ---------------- launch ----------------
extern "C" void kernel_launch(void* const* d_in, const int* in_sizes, int n_in,
                              void* d_out, int out_size) {
    const float* x  = (const float*)d_in[0];
    const float* w1 = (const float*)d_in[1];
    const float* b1 = (const float*)d_in[2];
    const float* w2 = (const float*)d_in[3];
    const float* b2 = (const float*)d_in[4];
    const float* wq = (const float*)d_in[5];
    const float* wk = (const float*)d_in[6];
    const float* wv = (const float*)d_in[7];
    const float* wo = (const float*)d_in[8];
    const float* bo = (const float*)d_in[9];
    float* out = (float*)d_out;

    cudaFuncSetAttribute(k_attn, cudaFuncAttributeMaxDynamicSharedMemorySize,
                         SMEM_FLOATS * (int)sizeof(float));

    k_transpose_w<<<(2 * 36864 + 255) / 256, 256>>>(w1, w2);
    k_conv<0><<<dim3(2, 32, 8), dim3(256)>>>(x, b1);     // conv1 partials, x read NCHW
    k_conv<1><<<dim3(2, 32, 8), dim3(256)>>>(x, b1);     // conv2 partials, fused relu(Σ+b1)
    k_attn<<<256, 256, SMEM_FLOATS * (int)sizeof(float)>>>(wq, wk, wv, wo, bo, b2, out);
}